// round 16
// baseline (speedup 1.0000x reference)
#include <cuda_runtime.h>
#include <cuda_bf16.h>
#include <cuda_fp16.h>
#include <cstdint>

#define GH 8
#define GW 8
#define RR 64
#define BB 8
#define CIN 128
#define COUT 256
#define NPIX 1024
#define NN 8192           // GEMM N per region (BB*NPIX)
#define KP2 256           // packed K per pixel: [gelu(128) | x(128)]
#define EPSV 1e-5f

// ---------------- scratch (device globals; no runtime allocation) -------------
// S layout: [r][n][k]  (n-major rows of 256 halfs; k<128: gelu, k>=128: raw x)
__device__ __half g_Sh[(size_t)RR * NN * KP2];            // 256 MB
__device__ __half g_Wh[(size_t)RR * COUT * KP2];          // 8 MB  ([o][k] row-major)
__device__ float g_bias[RR * COUT];

// ---------------- helpers -----------------------------------------------------
__device__ __forceinline__ uint32_t smem_u32(const void* p) {
    uint32_t a;
    asm("{ .reg .u64 t; cvta.to.shared.u64 t, %1; cvt.u32.u64 %0, t; }" : "=r"(a) : "l"(p));
    return a;
}
__device__ __forceinline__ void cpa16(uint32_t dst, const void* src) {
    asm volatile("cp.async.cg.shared.global [%0], [%1], 16;" :: "r"(dst), "l"(src) : "memory");
}
#define LDSM4(d, addr)                                                          \
    asm volatile("ldmatrix.sync.aligned.m8n8.x4.shared.b16 {%0,%1,%2,%3}, [%4];" \
                 : "=r"((d)[0]), "=r"((d)[1]), "=r"((d)[2]), "=r"((d)[3])        \
                 : "r"(addr))
#define MMAH(c, a, b0v, b1v)                                                     \
    asm volatile("mma.sync.aligned.m16n8k16.row.col.f32.f16.f16.f32 "            \
                 "{%0,%1,%2,%3},{%4,%5,%6,%7},{%8,%9},{%0,%1,%2,%3};"            \
                 : "+f"((c)[0]), "+f"((c)[1]), "+f"((c)[2]), "+f"((c)[3])        \
                 : "r"((a)[0]), "r"((a)[1]), "r"((a)[2]), "r"((a)[3]),           \
                   "r"(b0v), "r"(b1v))

// ---------------- kernel 1: dw 3x3 + BN1 + GELU -> S[r][n][k] fp16 ------------
// 512 threads = 16 warps = 16 channels; warp-per-channel register-rolling conv
// (lane = column), then smem transpose per 8-row group -> STG.128 into [n][k].
__global__ __launch_bounds__(512) void k_dw(const float* __restrict__ x,
                                            const float* __restrict__ dw_w,
                                            const float* __restrict__ g1,
                                            const float* __restrict__ b1,
                                            const float* __restrict__ m1,
                                            const float* __restrict__ v1) {
    __shared__ __half sge[256 * 18];   // [pixel(256)][ch pad 18]
    __shared__ __half sxe[256 * 18];
    int bxx = blockIdx.x;                 // 4096 = r(64) x bb(8) x cgrp(8)
    int cgrp = bxx & 7, bb = (bxx >> 3) & 7, r = bxx >> 6;
    int gh = r >> 3, gw = r & 7;
    int tid = threadIdx.x;
    int lane = tid & 31, w = tid >> 5;    // w = channel-within-group (0..15)
    int c = cgrp * 16 + w;

    int rc = r * CIN + c;
    float w9[9];
    const float* wp = dw_w + (size_t)rc * 9;
#pragma unroll
    for (int i = 0; i < 9; i++) w9[i] = wp[i];
    float rs = rsqrtf(v1[rc] + EPSV);
    float sc = g1[rc] * rs;
    float sh = b1[rc] - g1[rc] * m1[rc] * rs;

    const float* xb = x + (((size_t)(bb * CIN + c)) * 256 + gh * 32) * 256 + gw * 32 + lane;

    const unsigned FULL = 0xFFFFFFFFu;
    float pv = 0.f, pl = 0.f, pr = 0.f;                  // row-1 triple
    float cv = xb[0];
    float cl = __shfl_up_sync(FULL, cv, 1);  if (lane == 0)  cl = 0.f;
    float cr = __shfl_down_sync(FULL, cv, 1); if (lane == 31) cr = 0.f;
    float nraw = xb[256];                                 // row 1 raw

    // store-phase constants
    int p = tid >> 1, part = tid & 1;                     // pixel-in-group, 16B half
    const uint32_t* sgw = (const uint32_t*)sge;
    const uint32_t* sxw = (const uint32_t*)sxe;
    int wb = p * 9 + part * 4;                            // word base in smem
    __half* Sb = g_Sh + ((size_t)r * NN + (size_t)bb * NPIX) * KP2 + cgrp * 16 + part * 8;

#pragma unroll
    for (int rg = 0; rg < 4; rg++) {
#pragma unroll
        for (int r8 = 0; r8 < 8; r8++) {
            int row = rg * 8 + r8;
            float nraw2 = (row + 2 < 32) ? xb[(size_t)(row + 2) * 256] : 0.f;
            float nv = (row + 1 < 32) ? nraw : 0.f;
            float nl = __shfl_up_sync(FULL, nv, 1);  if (lane == 0)  nl = 0.f;
            float nr = __shfl_down_sync(FULL, nv, 1); if (lane == 31) nr = 0.f;

            float acc = 0.f;
            acc = fmaf(pl, w9[0], acc); acc = fmaf(pv, w9[1], acc); acc = fmaf(pr, w9[2], acc);
            acc = fmaf(cl, w9[3], acc); acc = fmaf(cv, w9[4], acc); acc = fmaf(cr, w9[5], acc);
            acc = fmaf(nl, w9[6], acc); acc = fmaf(nv, w9[7], acc); acc = fmaf(nr, w9[8], acc);

            float yv = fmaf(acc, sc, sh);
            float gv = 0.5f * yv * (1.f + erff(yv * 0.70710678118654752440f));

            int px = r8 * 32 + lane;                     // pixel within row-group
            sge[px * 18 + w] = __float2half(gv);         // stride 9 words: conflict-free
            sxe[px * 18 + w] = __float2half(cv);

            pv = cv; pl = cl; pr = cr;
            cv = nv; cl = nl; cr = nr;
            nraw = nraw2;
        }
        __syncthreads();
        // transpose store: each thread 16B per plane; pixel rows 512B apart
        {
            __half* dst = Sb + (size_t)(rg * 256 + p) * KP2;
            uint4 gv4 = make_uint4(sgw[wb], sgw[wb + 1], sgw[wb + 2], sgw[wb + 3]);
            uint4 xv4 = make_uint4(sxw[wb], sxw[wb + 1], sxw[wb + 2], sxw[wb + 3]);
            *(uint4*)dst = gv4;
            *(uint4*)(dst + 128) = xv4;
        }
        __syncthreads();
    }
}

// ---------------- kernel 0: fold BN2 into fp16 weights ------------------------
__global__ __launch_bounds__(256) void k_prep(const float* __restrict__ pw_w,
                                              const float* __restrict__ res_w,
                                              const float* __restrict__ g2,
                                              const float* __restrict__ b2,
                                              const float* __restrict__ m2,
                                              const float* __restrict__ v2) {
    int idx = blockIdx.x * 256 + threadIdx.x;      // RR*COUT*256
    int r = idx >> 16;
    int rem = idx & 65535;
    int o = rem >> 8;
    int k = rem & 255;
    int ro = r * COUT + o;
    float rs = rsqrtf(v2[ro] + EPSV);
    float scv = g2[ro] * rs;
    float wv = (k < CIN) ? scv * pw_w[(size_t)ro * CIN + k]
                         : res_w[(size_t)ro * CIN + (k - CIN)];
    g_Wh[(size_t)ro * KP2 + k] = __float2half(wv);
    if (k == 0) g_bias[ro] = b2[ro] - g2[ro] * m2[ro] * rs;
}

// ---------------- kernel 2: fp16 warp-MMA GEMM (n-major B, R9 config) ---------
// CTA tile 128m x 256n, 512 threads / 16 warps (warp tile 32x64), K-chunk 64.
// SMEM per stage (halfs): A @0 (128x72), B @9216 (256x72).
#define STG_E 27648
#define STG_B (STG_E * 2)          // 55296 bytes/stage

__global__ __launch_bounds__(512, 1) void k_gemm(float* __restrict__ out) {
    extern __shared__ __half smb[];
    uint32_t sbase = smem_u32(smb);
    int tid = threadIdx.x, lane = tid & 31, wid = tid >> 5;
    int wm = wid & 3, wn = wid >> 2;                 // 4x4 warp grid; warp = 32m x 64n
    int m0 = blockIdx.x * 128, n0 = blockIdx.y * 256, r = blockIdx.z;
    int gh = r >> 3, gw = r & 7;

    const __half* Wp = g_Wh + (size_t)(r * COUT + m0) * KP2;
    const __half* Sp = g_Sh + ((size_t)r * NN + n0) * KP2;

    float acc[2][8][4];
#pragma unroll
    for (int i = 0; i < 2; i++)
#pragma unroll
        for (int j = 0; j < 8; j++)
#pragma unroll
            for (int t = 0; t < 4; t++) acc[i][j][t] = 0.f;

    // cp.async load of one stage: A (128 rows x 64 k) + B (256 rows x 64 k)
    auto load_stage = [&](int s, int kc) {
        uint32_t st = sbase + (uint32_t)s * STG_B;
#pragma unroll
        for (int i = tid; i < 1024; i += 512) {      // A: 128 rows x 8 segs
            int rw = i >> 3, sg = i & 7;
            cpa16(st + 2u * (rw * 72 + sg * 8),
                  Wp + (size_t)rw * KP2 + kc + sg * 8);
        }
#pragma unroll
        for (int i = tid; i < 2048; i += 512) {      // B: 256 rows x 8 segs
            int rw = (i >> 3) & 255, sg = i & 7;
            cpa16(st + 2u * (9216 + rw * 72 + sg * 8),
                  Sp + (size_t)rw * KP2 + kc + sg * 8);
        }
        asm volatile("cp.async.commit_group;" ::: "memory");
    };

    int lrow = lane & 15, lc8 = (lane >> 4) * 8;     // ldmatrix address split
    load_stage(0, 0);

    for (int c = 0; c < 4; c++) {
        if (c < 3) load_stage((c + 1) & 1, (c + 1) * 64);
        if (c < 3) asm volatile("cp.async.wait_group 1;" ::: "memory");
        else       asm volatile("cp.async.wait_group 0;" ::: "memory");
        __syncthreads();

        uint32_t st = sbase + (uint32_t)(c & 1) * STG_B;
        uint32_t aA = st + 2u * ((wm * 32 + lrow) * 72 + lc8);
        uint32_t aB = st + 2u * (9216 + (wn * 64 + lrow) * 72 + lc8);

#pragma unroll
        for (int ks = 0; ks < 4; ks++) {
            uint32_t ko = 2u * (ks * 16);
            uint32_t ah[2][4], b[4][4];
#pragma unroll
            for (int mt = 0; mt < 2; mt++) LDSM4(ah[mt], aA + 2u * (mt * 16 * 72) + ko);
#pragma unroll
            for (int pq = 0; pq < 4; pq++) LDSM4(b[pq], aB + 2u * (pq * 16 * 72) + ko);
#pragma unroll
            for (int mt = 0; mt < 2; mt++)
#pragma unroll
                for (int nt = 0; nt < 8; nt++)
                    MMAH(acc[mt][nt], ah[mt], b[nt >> 1][nt & 1], b[nt >> 1][2 + (nt & 1)]);
        }
        __syncthreads();
    }

    // ---- epilogue: bias + scatter to [B, COUT, 256, 256] ----
    int qrow = lane >> 2, qcol = (lane & 3) * 2;
#pragma unroll
    for (int mt = 0; mt < 2; mt++) {
        int mrow = m0 + wm * 32 + mt * 16 + qrow;
        float bi0 = g_bias[r * COUT + mrow];
        float bi1 = g_bias[r * COUT + mrow + 8];
#pragma unroll
        for (int nt = 0; nt < 8; nt++) {
            int nidx = n0 + wn * 64 + nt * 8 + qcol;
            int b2i = nidx >> 10, hw = nidx & 1023;
            int prow = hw >> 5, pcol = hw & 31;
            size_t off0 = (((size_t)(b2i * COUT + mrow) * 256 + gh * 32 + prow) * 256 +
                           gw * 32 + pcol);
            size_t off1 = off0 + (size_t)8 * 65536;          // mrow+8
            float2 v0 = make_float2(acc[mt][nt][0] + bi0, acc[mt][nt][1] + bi0);
            float2 v1 = make_float2(acc[mt][nt][2] + bi1, acc[mt][nt][3] + bi1);
            *(float2*)&out[off0] = v0;
            *(float2*)&out[off1] = v1;
        }
    }
}

// ---------------- launch (single stream; dw first for ncu attribution) --------
extern "C" void kernel_launch(void* const* d_in, const int* in_sizes, int n_in,
                              void* d_out, int out_size) {
    const float* x     = (const float*)d_in[0];
    const float* dw_w  = (const float*)d_in[1];
    const float* bn1_g = (const float*)d_in[2];
    const float* bn1_b = (const float*)d_in[3];
    const float* bn1_m = (const float*)d_in[4];
    const float* bn1_v = (const float*)d_in[5];
    const float* pw_w  = (const float*)d_in[6];
    const float* bn2_g = (const float*)d_in[7];
    const float* bn2_b = (const float*)d_in[8];
    const float* bn2_m = (const float*)d_in[9];
    const float* bn2_v = (const float*)d_in[10];
    const float* res_w = (const float*)d_in[11];
    float* out = (float*)d_out;

    cudaFuncSetAttribute(k_gemm, cudaFuncAttributeMaxDynamicSharedMemorySize,
                         2 * STG_B);

    k_dw<<<RR * BB * 8, 512>>>(x, dw_w, bn1_g, bn1_b, bn1_m, bn1_v);
    k_prep<<<(RR * COUT * 256) / 256, 256>>>(pw_w, res_w, bn2_g, bn2_b, bn2_m, bn2_v);
    // x = m-block fastest: the 2 CTAs sharing one B tile run adjacently (L2 reuse)
    dim3 grid(COUT / 128, NN / 256, RR);
    k_gemm<<<grid, 512, 2 * STG_B>>>(out);
}

// round 17
// speedup vs baseline: 1.0680x; 1.0680x over previous
#include <cuda_runtime.h>
#include <cuda_bf16.h>
#include <cuda_fp16.h>
#include <cstdint>

#define GH 8
#define GW 8
#define RR 64
#define BB 8
#define CIN 128
#define COUT 256
#define NPIX 1024
#define NN 8192           // GEMM N per region (BB*NPIX)
#define KP2 256           // packed K: [gelu(128) | x(128)]
#define EPSV 1e-5f

// ---------------- scratch (device globals; no runtime allocation) -------------
// S layout: [r][k][n]  (k-major, n contiguous). k<128: gelu, k>=128: raw x.
__device__ __half g_Sh[(size_t)RR * KP2 * NN];            // 256 MB
__device__ __half g_Wh[(size_t)RR * COUT * KP2];          // 8 MB  ([o][k] row-major)
__device__ float g_bias[RR * COUT];

// ---------------- helpers -----------------------------------------------------
__device__ __forceinline__ uint32_t smem_u32(const void* p) {
    uint32_t a;
    asm("{ .reg .u64 t; cvta.to.shared.u64 t, %1; cvt.u32.u64 %0, t; }" : "=r"(a) : "l"(p));
    return a;
}
__device__ __forceinline__ void cpa16(uint32_t dst, const void* src) {
    asm volatile("cp.async.cg.shared.global [%0], [%1], 16;" :: "r"(dst), "l"(src) : "memory");
}
#define LDSM4(d, addr)                                                          \
    asm volatile("ldmatrix.sync.aligned.m8n8.x4.shared.b16 {%0,%1,%2,%3}, [%4];" \
                 : "=r"((d)[0]), "=r"((d)[1]), "=r"((d)[2]), "=r"((d)[3])        \
                 : "r"(addr))
#define LDSM4T(d, addr)                                                         \
    asm volatile("ldmatrix.sync.aligned.m8n8.x4.trans.shared.b16 {%0,%1,%2,%3}, [%4];" \
                 : "=r"((d)[0]), "=r"((d)[1]), "=r"((d)[2]), "=r"((d)[3])        \
                 : "r"(addr))
#define MMAH(c, a, b0v, b1v)                                                     \
    asm volatile("mma.sync.aligned.m16n8k16.row.col.f32.f16.f16.f32 "            \
                 "{%0,%1,%2,%3},{%4,%5,%6,%7},{%8,%9},{%0,%1,%2,%3};"            \
                 : "+f"((c)[0]), "+f"((c)[1]), "+f"((c)[2]), "+f"((c)[3])        \
                 : "r"((a)[0]), "r"((a)[1]), "r"((a)[2]), "r"((a)[3]),           \
                   "r"(b0v), "r"(b1v))

// ---------------- kernel 1: dw 3x3 + BN1 + GELU -> S[r][k][n] fp16 ------------
// One warp per (region, batch, channel); lane = column. No smem, no barriers.
// (R15 version, measured 110us)
__global__ __launch_bounds__(256) void k_dw(const float* __restrict__ x,
                                            const float* __restrict__ dw_w,
                                            const float* __restrict__ g1,
                                            const float* __restrict__ b1,
                                            const float* __restrict__ m1,
                                            const float* __restrict__ v1) {
    int bxx = blockIdx.x;                 // 8192 = r(64) x bb(8) x cgrp(16)
    int cgrp = bxx & 15, bb = (bxx >> 4) & 7, r = bxx >> 7;
    int gh = r >> 3, gw = r & 7;
    int lane = threadIdx.x & 31;
    int c = cgrp * 8 + (threadIdx.x >> 5); // warp -> channel

    int rc = r * CIN + c;
    float w9[9];
    const float* wp = dw_w + (size_t)rc * 9;
#pragma unroll
    for (int i = 0; i < 9; i++) w9[i] = wp[i];
    float rs = rsqrtf(v1[rc] + EPSV);
    float sc = g1[rc] * rs;
    float sh = b1[rc] - g1[rc] * m1[rc] * rs;

    const float* xb = x + (((size_t)(bb * CIN + c)) * 256 + gh * 32) * 256 + gw * 32 + lane;
    __half* gout = g_Sh + ((size_t)(r * KP2 + c)) * NN + (size_t)bb * NPIX + lane;
    __half* xout = gout + (size_t)CIN * NN;

    const unsigned FULL = 0xFFFFFFFFu;
    float pv = 0.f, pl = 0.f, pr = 0.f;                  // row-1 triple
    float cv = xb[0];
    float cl = __shfl_up_sync(FULL, cv, 1);  if (lane == 0)  cl = 0.f;
    float cr = __shfl_down_sync(FULL, cv, 1); if (lane == 31) cr = 0.f;
    float nraw = xb[256];                                 // row 1 raw

#pragma unroll
    for (int row = 0; row < 32; row++) {
        float nraw2 = (row + 2 < 32) ? xb[(size_t)(row + 2) * 256] : 0.f;  // prefetch
        float nv = (row + 1 < 32) ? nraw : 0.f;
        float nl = __shfl_up_sync(FULL, nv, 1);  if (lane == 0)  nl = 0.f;
        float nr = __shfl_down_sync(FULL, nv, 1); if (lane == 31) nr = 0.f;

        float acc = 0.f;
        acc = fmaf(pl, w9[0], acc); acc = fmaf(pv, w9[1], acc); acc = fmaf(pr, w9[2], acc);
        acc = fmaf(cl, w9[3], acc); acc = fmaf(cv, w9[4], acc); acc = fmaf(cr, w9[5], acc);
        acc = fmaf(nl, w9[6], acc); acc = fmaf(nv, w9[7], acc); acc = fmaf(nr, w9[8], acc);

        float yv = fmaf(acc, sc, sh);
        float gv = 0.5f * yv * (1.f + erff(yv * 0.70710678118654752440f));
        gout[row * 32] = __float2half(gv);
        xout[row * 32] = __float2half(cv);               // raw center x

        pv = cv; pl = cl; pr = cr;
        cv = nv; cl = nl; cr = nr;
        nraw = nraw2;
    }
}

// ---------------- kernel 0: fold BN2 into fp16 weights ------------------------
__global__ __launch_bounds__(256) void k_prep(const float* __restrict__ pw_w,
                                              const float* __restrict__ res_w,
                                              const float* __restrict__ g2,
                                              const float* __restrict__ b2,
                                              const float* __restrict__ m2,
                                              const float* __restrict__ v2) {
    int idx = blockIdx.x * 256 + threadIdx.x;      // RR*COUT*256
    int r = idx >> 16;
    int rem = idx & 65535;
    int o = rem >> 8;
    int k = rem & 255;
    int ro = r * COUT + o;
    float rs = rsqrtf(v2[ro] + EPSV);
    float scv = g2[ro] * rs;
    float wv = (k < CIN) ? scv * pw_w[(size_t)ro * CIN + k]
                         : res_w[(size_t)ro * CIN + (k - CIN)];
    g_Wh[(size_t)ro * KP2 + k] = __float2half(wv);
    if (k == 0) g_bias[ro] = b2[ro] - g2[ro] * m2[ro] * rs;
}

// ---------------- kernel 2: fp16 warp-MMA GEMM (trans-B, 16 warps) ------------
// R14 version, measured ~289us. CTA tile 128m x 256n, 512 threads / 16 warps
// (warp tile 32x64), K-chunk 64. SMEM per stage (halfs): A @0 (128x72, k-contig),
// B @9216 (64 k-rows x 264 n).
#define NSTR 264
#define STG_E (9216 + 64 * NSTR)   // 26112 halfs
#define STG_B (STG_E * 2)          // 52224 bytes/stage

__global__ __launch_bounds__(512, 1) void k_gemm(float* __restrict__ out) {
    extern __shared__ __half smb[];
    uint32_t sbase = smem_u32(smb);
    int tid = threadIdx.x, lane = tid & 31, wid = tid >> 5;
    int wm = wid & 3, wn = wid >> 2;                 // 4x4 warp grid; warp = 32m x 64n
    int m0 = blockIdx.x * 128, n0 = blockIdx.y * 256, r = blockIdx.z;
    int gh = r >> 3, gw = r & 7;

    const __half* Wp = g_Wh + (size_t)(r * COUT + m0) * KP2;
    const __half* Sp = g_Sh + (size_t)r * KP2 * NN;   // [k][n] for this region

    float acc[2][8][4];
#pragma unroll
    for (int i = 0; i < 2; i++)
#pragma unroll
        for (int j = 0; j < 8; j++)
#pragma unroll
            for (int t = 0; t < 4; t++) acc[i][j][t] = 0.f;

    // cp.async load of one stage: A (128 rows x 64 k) + B (64 k-rows x 256 n)
    auto load_stage = [&](int s, int kc) {
        uint32_t st = sbase + (uint32_t)s * STG_B;
#pragma unroll
        for (int i = tid; i < 1024; i += 512) {      // A: 128 rows x 8 segs
            int rw = i >> 3, sg = i & 7;
            cpa16(st + 2u * (rw * 72 + sg * 8),
                  Wp + (size_t)rw * KP2 + kc + sg * 8);
        }
#pragma unroll
        for (int i = tid; i < 2048; i += 512) {      // B: 64 k-rows x 32 segs
            int kr = i >> 5, sg = i & 31;
            cpa16(st + 2u * (9216 + kr * NSTR + sg * 8),
                  Sp + (size_t)(kc + kr) * NN + n0 + sg * 8);
        }
        asm volatile("cp.async.commit_group;" ::: "memory");
    };

    int lrow = lane & 15, lc8 = (lane >> 4) * 8;                 // A ldmatrix map
    int krow = (lane & 7) | ((lane >> 4) << 3);                  // B trans map
    int ncol8 = ((lane >> 3) & 1) << 3;
    load_stage(0, 0);

    for (int c = 0; c < 4; c++) {
        if (c < 3) load_stage((c + 1) & 1, (c + 1) * 64);
        if (c < 3) asm volatile("cp.async.wait_group 1;" ::: "memory");
        else       asm volatile("cp.async.wait_group 0;" ::: "memory");
        __syncthreads();

        uint32_t st = sbase + (uint32_t)(c & 1) * STG_B;
        uint32_t aA = st + 2u * ((wm * 32 + lrow) * 72 + lc8);
        uint32_t aB = st + 2u * (9216 + krow * NSTR + wn * 64 + ncol8);

#pragma unroll
        for (int ks = 0; ks < 4; ks++) {
            uint32_t ah[2][4], b[4][4];
#pragma unroll
            for (int mt = 0; mt < 2; mt++)
                LDSM4(ah[mt], aA + 2u * (mt * 16 * 72 + ks * 16));
#pragma unroll
            for (int p = 0; p < 4; p++)
                LDSM4T(b[p], aB + 2u * (ks * 16 * NSTR + p * 16));
#pragma unroll
            for (int mt = 0; mt < 2; mt++)
#pragma unroll
                for (int nt = 0; nt < 8; nt++)
                    MMAH(acc[mt][nt], ah[mt], b[nt >> 1][nt & 1], b[nt >> 1][2 + (nt & 1)]);
        }
        __syncthreads();
    }

    // ---- epilogue: bias + scatter to [B, COUT, 256, 256] ----
    int qrow = lane >> 2, qcol = (lane & 3) * 2;
#pragma unroll
    for (int mt = 0; mt < 2; mt++) {
        int mrow = m0 + wm * 32 + mt * 16 + qrow;
        float bi0 = g_bias[r * COUT + mrow];
        float bi1 = g_bias[r * COUT + mrow + 8];
#pragma unroll
        for (int nt = 0; nt < 8; nt++) {
            int nidx = n0 + wn * 64 + nt * 8 + qcol;
            int b2i = nidx >> 10, hw = nidx & 1023;
            int prow = hw >> 5, pcol = hw & 31;
            size_t off0 = (((size_t)(b2i * COUT + mrow) * 256 + gh * 32 + prow) * 256 +
                           gw * 32 + pcol);
            size_t off1 = off0 + (size_t)8 * 65536;          // mrow+8
            float2 v0 = make_float2(acc[mt][nt][0] + bi0, acc[mt][nt][1] + bi0);
            float2 v1 = make_float2(acc[mt][nt][2] + bi1, acc[mt][nt][3] + bi1);
            *(float2*)&out[off0] = v0;
            *(float2*)&out[off1] = v1;
        }
    }
}

// ---------------- launch (single stream; dw first for ncu attribution) --------
extern "C" void kernel_launch(void* const* d_in, const int* in_sizes, int n_in,
                              void* d_out, int out_size) {
    const float* x     = (const float*)d_in[0];
    const float* dw_w  = (const float*)d_in[1];
    const float* bn1_g = (const float*)d_in[2];
    const float* bn1_b = (const float*)d_in[3];
    const float* bn1_m = (const float*)d_in[4];
    const float* bn1_v = (const float*)d_in[5];
    const float* pw_w  = (const float*)d_in[6];
    const float* bn2_g = (const float*)d_in[7];
    const float* bn2_b = (const float*)d_in[8];
    const float* bn2_m = (const float*)d_in[9];
    const float* bn2_v = (const float*)d_in[10];
    const float* res_w = (const float*)d_in[11];
    float* out = (float*)d_out;

    cudaFuncSetAttribute(k_gemm, cudaFuncAttributeMaxDynamicSharedMemorySize,
                         2 * STG_B);

    k_dw<<<RR * BB * 16, 256>>>(x, dw_w, bn1_g, bn1_b, bn1_m, bn1_v);
    k_prep<<<(RR * COUT * 256) / 256, 256>>>(pw_w, res_w, bn2_g, bn2_b, bn2_m, bn2_v);
    // x = m-block fastest: the 2 CTAs sharing one B tile run adjacently (L2 reuse)
    dim3 grid(COUT / 128, NN / 256, RR);
    k_gemm<<<grid, 512, 2 * STG_B>>>(out);
}